// round 11
// baseline (speedup 1.0000x reference)
#include <cuda_runtime.h>
#include <math.h>
#include <stdint.h>

#define BATCH  4
#define LSEQ   4096
#define DMODEL 1024
#define DINNER 2048
#define DTR    64
#define NST    16
#define XDBLC  96   // dt_rank + 2*N

// ---------------- scratch (device globals) ----------------
__device__ float g_xr  [(size_t)BATCH * LSEQ * (2 * DINNER)];  // in-proj out (x | res)
__device__ float g_xc  [(size_t)BATCH * LSEQ * DINNER];        // conv+silu (tf32) -> y(gated,tf32) in place
__device__ float g_xdbl[(size_t)BATCH * LSEQ * XDBLC];         // tf32-rounded
__device__ float g_dt  [(size_t)BATCH * LSEQ * DINNER];        // full fp32 (scan-only)
__device__ float g_xt  [(size_t)BATCH * LSEQ * DMODEL];        // tf32-rounded x
__device__ float g_Win [(size_t)DMODEL * (2 * DINNER)];        // tf32-rounded weights
__device__ float g_Wx  [(size_t)DINNER * XDBLC];
__device__ float g_Wdt [(size_t)DTR * DINNER];
__device__ float g_Wout[(size_t)DINNER * DMODEL];

// ---------------- helpers ----------------
__device__ __forceinline__ uint32_t smem_u32(const void* p) {
    uint32_t a;
    asm("{ .reg .u64 t; cvta.to.shared.u64 t, %1; cvt.u32.u64 %0, t; }" : "=r"(a) : "l"(p));
    return a;
}
__device__ __forceinline__ float f2tf(float f) {
    uint32_t r; asm("cvt.rna.tf32.f32 %0, %1;" : "=r"(r) : "f"(f));
    return __uint_as_float(r);
}
__device__ __forceinline__ void cp16(uint32_t dst, const void* src, uint32_t sz) {
    asm volatile("cp.async.cg.shared.global [%0], [%1], 16, %2;"
                 :: "r"(dst), "l"(src), "r"(sz) : "memory");
}
__device__ __forceinline__ void mma8(float* c,
    uint32_t a0, uint32_t a1, uint32_t a2, uint32_t a3, uint32_t b0, uint32_t b1)
{
    asm volatile(
        "mma.sync.aligned.m16n8k8.row.col.f32.tf32.tf32.f32 "
        "{%0,%1,%2,%3}, {%4,%5,%6,%7}, {%8,%9}, {%0,%1,%2,%3};"
        : "+f"(c[0]), "+f"(c[1]), "+f"(c[2]), "+f"(c[3])
        : "r"(a0), "r"(a1), "r"(a2), "r"(a3), "r"(b0), "r"(b1));
}

// ---------------- smem layout: 3 stages, A [256][36], B [32][136] ----------
#define A_ST  36864                 // 256*36*4
#define B_ST  17408                 // 32*136*4
#define B_BASE (3 * A_ST)           // 110592
#define SMEM_GEMM (3 * A_ST + 3 * B_ST)   // 162816 -> 1 block/SM

// C[M,N] = A[M,K] @ B[K,N] (+bias). epi: 0=none, 1=softplus, 2=tf32-round output.
// Inputs pre-rounded tf32 -> pure 1xTF32 MMA.
// Block tile 256x128, 8 warps (4x2), warp tile 64x64.
// M % 256 == 0, K % 32 == 0; N mult of 2 (guarded).
__global__ __launch_bounds__(256, 1)
void mma_gemm(const float* __restrict__ A, const float* __restrict__ B,
              const float* __restrict__ bias, float* __restrict__ C,
              int M, int N, int K, int lda, int ldb, int ldc, int epi)
{
    extern __shared__ char smc[];
    const uint32_t sb = smem_u32(smc);
    const int tid = threadIdx.x;
    const int bm = blockIdx.y * 256;
    const int bn = blockIdx.x * 128;
    const int wid = tid >> 5, lane = tid & 31;
    const int wm = wid >> 1, wn = wid & 1;     // 4x2 warps, warp tile 64x64
    const int qr = lane >> 2, qc = lane & 3;

    float acc[4][8][4];
    #pragma unroll
    for (int i = 0; i < 4; i++)
        #pragma unroll
        for (int j = 0; j < 8; j++)
            #pragma unroll
            for (int e = 0; e < 4; e++) acc[i][j][e] = 0.f;

    const int rA = tid >> 3, cA = (tid & 7) * 4;     // A loader: +32 rows per t (8 t)
    const int kB = tid >> 5, nB = (tid & 31) * 4;    // B loader: +8 rows per t (4 t)
    const uint32_t bsz = (bn + nB < N) ? 16u : 0u;
    const int nclamp = (bn + nB < N) ? (bn + nB) : 0;

    const int nch = K >> 5;

    auto issue = [&](int ch) {
        const int kt = ch << 5;
        const int st = ch - (ch / 3) * 3;
        const uint32_t dA = sb + st * A_ST;
        const uint32_t dB = sb + B_BASE + st * B_ST;
        #pragma unroll
        for (int t = 0; t < 8; t++) {
            const int r = rA + t * 32;
            cp16(dA + (uint32_t)(r * 36 + cA) * 4,
                 A + (size_t)(bm + r) * lda + kt + cA, 16u);
        }
        #pragma unroll
        for (int t = 0; t < 4; t++) {
            const int k = kB + t * 8;
            cp16(dB + (uint32_t)(k * 136 + nB) * 4,
                 B + (size_t)(kt + k) * ldb + nclamp, bsz);
        }
        asm volatile("cp.async.commit_group;" ::: "memory");
    };

    issue(0);
    issue(1);   // nch >= 2 always (K >= 64)

    for (int i = 0; i < nch; i++) {
        if (i + 1 < nch) { asm volatile("cp.async.wait_group 1;" ::: "memory"); }
        else             { asm volatile("cp.async.wait_group 0;" ::: "memory"); }
        __syncthreads();                 // stage i visible; compute(i-1) done everywhere
        if (i + 2 < nch) issue(i + 2);   // reuses stage (i-1)%3 — safe after barrier

        const int st = i - (i / 3) * 3;
        const uint32_t* Ahi = (const uint32_t*)(smc + st * A_ST);
        const uint32_t* Bsm = (const uint32_t*)(smc + B_BASE + st * B_ST);

        #pragma unroll
        for (int kk = 0; kk < 32; kk += 8) {
            uint32_t ah[4][4];
            #pragma unroll
            for (int tm = 0; tm < 4; tm++) {
                const int r0 = wm * 64 + tm * 16 + qr;
                ah[tm][0] = Ahi[r0 * 36 + kk + qc];
                ah[tm][1] = Ahi[(r0 + 8) * 36 + kk + qc];
                ah[tm][2] = Ahi[r0 * 36 + kk + qc + 4];
                ah[tm][3] = Ahi[(r0 + 8) * 36 + kk + qc + 4];
            }
            #pragma unroll
            for (int tn = 0; tn < 8; tn++) {
                const int col = wn * 64 + tn * 8 + qr;
                const uint32_t b0 = Bsm[(kk + qc) * 136 + col];
                const uint32_t b1 = Bsm[(kk + qc + 4) * 136 + col];
                #pragma unroll
                for (int tm = 0; tm < 4; tm++)
                    mma8(acc[tm][tn], ah[tm][0], ah[tm][1], ah[tm][2], ah[tm][3], b0, b1);
            }
        }
    }

    // ---- epilogue ----
    #pragma unroll
    for (int tm = 0; tm < 4; tm++) {
        const int r0 = bm + wm * 64 + tm * 16 + qr;
        #pragma unroll
        for (int tn = 0; tn < 8; tn++) {
            const int c0 = bn + wn * 64 + tn * 8 + 2 * qc;
            #pragma unroll
            for (int half = 0; half < 2; half++) {
                const int r = r0 + half * 8;
                float v0 = acc[tm][tn][half * 2 + 0];
                float v1 = acc[tm][tn][half * 2 + 1];
                if (bias && c0 < N) { v0 += bias[c0]; if (c0 + 1 < N) v1 += bias[c0 + 1]; }
                if (epi == 1) {
                    v0 = (v0 > 20.f) ? v0 : log1pf(expf(v0));
                    v1 = (v1 > 20.f) ? v1 : log1pf(expf(v1));
                } else if (epi == 2) {
                    v0 = f2tf(v0); v1 = f2tf(v1);
                }
                if (c0 + 1 < N) {
                    *(float2*)(C + (size_t)r * ldc + c0) = make_float2(v0, v1);
                } else if (c0 < N) {
                    C[(size_t)r * ldc + c0] = v0;
                }
            }
        }
    }
}

// ---------------- round-copy: dst = tf32_rna(src), float4 ----------------
__global__ __launch_bounds__(256)
void round_copy(const float* __restrict__ src, float* __restrict__ dst, size_t n4)
{
    size_t i = (size_t)blockIdx.x * blockDim.x + threadIdx.x;
    if (i >= n4) return;
    const float4 v = ((const float4*)src)[i];
    float4 o;
    o.x = f2tf(v.x); o.y = f2tf(v.y); o.z = f2tf(v.z); o.w = f2tf(v.w);
    ((float4*)dst)[i] = o;
}

// ---------------- causal depthwise conv (K=4) + SiLU -> tf32 --------------
__global__ __launch_bounds__(256)
void conv_silu_kernel(const float* __restrict__ conv_w, const float* __restrict__ conv_b)
{
    const size_t total4 = (size_t)BATCH * LSEQ * (DINNER / 4);
    size_t idx = (size_t)blockIdx.x * blockDim.x + threadIdx.x;
    if (idx >= total4) return;
    const int d4 = (int)(idx % (DINNER / 4));
    const int l  = (int)((idx / (DINNER / 4)) % LSEQ);
    const int b  = (int)(idx / ((size_t)(DINNER / 4) * LSEQ));
    const int d  = d4 * 4;

    float acc0 = conv_b[d], acc1 = conv_b[d + 1], acc2 = conv_b[d + 2], acc3 = conv_b[d + 3];
    #pragma unroll
    for (int k = 0; k < 4; k++) {
        const int ls = l - 3 + k;
        if (ls >= 0) {
            const float4 v = *(const float4*)(&g_xr[((size_t)b * LSEQ + ls) * (2 * DINNER) + d]);
            acc0 = fmaf(conv_w[(d + 0) * 4 + k], v.x, acc0);
            acc1 = fmaf(conv_w[(d + 1) * 4 + k], v.y, acc1);
            acc2 = fmaf(conv_w[(d + 2) * 4 + k], v.z, acc2);
            acc3 = fmaf(conv_w[(d + 3) * 4 + k], v.w, acc3);
        }
    }
    float4 o;
    o.x = f2tf(acc0 / (1.f + __expf(-acc0)));
    o.y = f2tf(acc1 / (1.f + __expf(-acc1)));
    o.z = f2tf(acc2 / (1.f + __expf(-acc2)));
    o.w = f2tf(acc3 / (1.f + __expf(-acc3)));
    *(float4*)(&g_xc[((size_t)b * LSEQ + l) * DINNER + d]) = o;
}

// ---------------- selective scan over L (+x*D, fused gate) --------------
#define SCAN_T 128
__global__ __launch_bounds__(64)
void scan_kernel(const float* __restrict__ A_log, const float* __restrict__ D_par)
{
    __shared__ float sBC[SCAN_T][32];

    const int tid = threadIdx.x;
    const int d = blockIdx.x * 64 + tid;
    const int b = blockIdx.y;

    float A[NST];
    #pragma unroll
    for (int n = 0; n < NST; n++) A[n] = -expf(A_log[d * NST + n]);
    // structural fast path: A[n] == (n+1)*A[0]  (true for A_log = log(1..16))
    bool fast = true;
    #pragma unroll
    for (int n = 0; n < NST; n++)
        fast = fast && (fabsf(A[n] - (float)(n + 1) * A[0]) <= 1e-4f * (float)(n + 1));

    float h[NST];
    #pragma unroll
    for (int n = 0; n < NST; n++) h[n] = 0.f;
    const float Dp = D_par[d];

    size_t pd = (size_t)b * LSEQ * DINNER + d;
    size_t pr = (size_t)b * LSEQ * (2 * DINNER) + DINNER + d;

    float dt_nx = g_dt[pd];
    float xt_nx = g_xc[pd];
    float rr_nx = g_xr[pr];

    const float* xdb = g_xdbl + (size_t)b * LSEQ * XDBLC + DTR;

    for (int c = 0; c < LSEQ / SCAN_T; c++) {
        __syncthreads();
        const float* src = xdb + (size_t)c * SCAN_T * XDBLC;
        #pragma unroll 4
        for (int i = tid; i < SCAN_T * 8; i += 64) {
            const int row = i >> 3, c4 = (i & 7) * 4;
            *(float4*)&sBC[row][c4] = *(const float4*)(src + (size_t)row * XDBLC + c4);
        }
        __syncthreads();

        for (int t = 0; t < SCAN_T; t++) {
            const float dt = dt_nx, xt = xt_nx, rr = rr_nx;
            const size_t pd_cur = pd;
            const int l = c * SCAN_T + t;
            pd += DINNER; pr += 2 * DINNER;
            if (l + 1 < LSEQ) {
                dt_nx = g_dt[pd];
                xt_nx = g_xc[pd];
                rr_nx = g_xr[pr];
            }
            float dA[NST];
            if (fast) {
                const float e1 = __expf(dt * A[0]);
                const float e2 = e1 * e1, e3 = e2 * e1, e4 = e2 * e2;
                const float e5 = e4 * e1, e6 = e4 * e2, e7 = e4 * e3, e8 = e4 * e4;
                dA[0] = e1;  dA[1] = e2;  dA[2] = e3;  dA[3] = e4;
                dA[4] = e5;  dA[5] = e6;  dA[6] = e7;  dA[7] = e8;
                dA[8]  = e8 * e1;  dA[9]  = e8 * e2;  dA[10] = e8 * e3;  dA[11] = e8 * e4;
                dA[12] = e8 * e5;  dA[13] = e8 * e6;  dA[14] = e8 * e7;  dA[15] = e8 * e8;
            } else {
                #pragma unroll
                for (int n = 0; n < NST; n++) dA[n] = __expf(dt * A[n]);
            }
            const float dtx = dt * xt;
            float y0 = 0.f, y1 = 0.f, y2 = 0.f, y3 = 0.f;
            #pragma unroll
            for (int n = 0; n < NST; n += 4) {
                h[n + 0] = fmaf(h[n + 0], dA[n + 0], dtx * sBC[t][n + 0]);
                h[n + 1] = fmaf(h[n + 1], dA[n + 1], dtx * sBC[t][n + 1]);
                h[n + 2] = fmaf(h[n + 2], dA[n + 2], dtx * sBC[t][n + 2]);
                h[n + 3] = fmaf(h[n + 3], dA[n + 3], dtx * sBC[t][n + 3]);
                y0 = fmaf(h[n + 0], sBC[t][NST + n + 0], y0);
                y1 = fmaf(h[n + 1], sBC[t][NST + n + 1], y1);
                y2 = fmaf(h[n + 2], sBC[t][NST + n + 2], y2);
                y3 = fmaf(h[n + 3], sBC[t][NST + n + 3], y3);
            }
            const float yt = (y0 + y1) + (y2 + y3);
            const float gate = rr / (1.f + __expf(-rr));
            g_xc[pd_cur] = f2tf(fmaf(xt, Dp, yt) * gate);   // tf32 for out-proj A
        }
    }
}

// ---------------- launch -------------------------------------------------
extern "C" void kernel_launch(void* const* d_in, const int* in_sizes, int n_in,
                              void* d_out, int out_size)
{
    const float* x      = (const float*)d_in[0];
    const float* W_in   = (const float*)d_in[1];
    const float* b_in   = (const float*)d_in[2];
    const float* conv_w = (const float*)d_in[3];
    const float* conv_b = (const float*)d_in[4];
    const float* W_x    = (const float*)d_in[5];
    const float* W_dt   = (const float*)d_in[6];
    const float* b_dt   = (const float*)d_in[7];
    const float* A_log  = (const float*)d_in[8];
    const float* D_par  = (const float*)d_in[9];
    const float* W_out  = (const float*)d_in[10];
    const float* b_out  = (const float*)d_in[11];
    float* out = (float*)d_out;

    float *xr, *xc, *xdbl, *dt, *xt, *Win, *Wx, *Wdt, *Wout;
    cudaGetSymbolAddress((void**)&xr,   g_xr);
    cudaGetSymbolAddress((void**)&xc,   g_xc);
    cudaGetSymbolAddress((void**)&xdbl, g_xdbl);
    cudaGetSymbolAddress((void**)&dt,   g_dt);
    cudaGetSymbolAddress((void**)&xt,   g_xt);
    cudaGetSymbolAddress((void**)&Win,  g_Win);
    cudaGetSymbolAddress((void**)&Wx,   g_Wx);
    cudaGetSymbolAddress((void**)&Wdt,  g_Wdt);
    cudaGetSymbolAddress((void**)&Wout, g_Wout);

    cudaFuncSetAttribute(mma_gemm, cudaFuncAttributeMaxDynamicSharedMemorySize, SMEM_GEMM);

    const int M = BATCH * LSEQ;   // 16384

    // 0) pre-round all GEMM operands to tf32
    auto rc = [](const float* s, float* d, size_t n) {
        const size_t n4 = n / 4;
        round_copy<<<(unsigned)((n4 + 255) / 256), 256>>>(s, d, n4);
    };
    rc(x,     xt,   (size_t)M * DMODEL);
    rc(W_in,  Win,  (size_t)DMODEL * 2 * DINNER);
    rc(W_x,   Wx,   (size_t)DINNER * XDBLC);
    rc(W_dt,  Wdt,  (size_t)DTR * DINNER);
    rc(W_out, Wout, (size_t)DINNER * DMODEL);

    // 1) in-projection: [M,1024] @ [1024,4096] -> g_xr (full fp32 out)
    mma_gemm<<<dim3((2 * DINNER) / 128, M / 256), 256, SMEM_GEMM>>>(
        xt, Win, b_in, xr, M, 2 * DINNER, DMODEL, DMODEL, 2 * DINNER, 2 * DINNER, 0);

    // 2) causal depthwise conv + silu -> g_xc (tf32)
    {
        const size_t total4 = (size_t)M * (DINNER / 4);
        conv_silu_kernel<<<(unsigned)((total4 + 255) / 256), 256>>>(conv_w, conv_b);
    }

    // 3) x_dbl: [M,2048] @ [2048,96] -> g_xdbl (tf32 out, epi=2)
    mma_gemm<<<dim3(1, M / 256), 256, SMEM_GEMM>>>(
        xc, Wx, nullptr, xdbl, M, XDBLC, DINNER, DINNER, XDBLC, XDBLC, 2);

    // 4) delta: softplus([M,64] @ [64,2048] + b_dt) -> g_dt (full fp32)
    mma_gemm<<<dim3(DINNER / 128, M / 256), 256, SMEM_GEMM>>>(
        xdbl, Wdt, b_dt, dt, M, DINNER, DTR, XDBLC, DINNER, DINNER, 1);

    // 5) selective scan (y in place over g_xc, + x*D, * silu(res), tf32 out)
    scan_kernel<<<dim3(DINNER / 64, BATCH), 64>>>(A_log, D_par);

    // 6) out-projection: [M,2048] @ [2048,1024] + b_out -> d_out
    mma_gemm<<<dim3(DMODEL / 128, M / 256), 256, SMEM_GEMM>>>(
        xc, Wout, b_out, out, M, DMODEL, DINNER, DINNER, DMODEL, DMODEL, 0);
}

// round 12
// speedup vs baseline: 1.1203x; 1.1203x over previous
#include <cuda_runtime.h>
#include <math.h>
#include <stdint.h>

#define BATCH  4
#define LSEQ   4096
#define DMODEL 1024
#define DINNER 2048
#define DTR    64
#define NST    16
#define XDBLC  96   // dt_rank + 2*N

// ---------------- scratch (device globals) ----------------
__device__ float g_xr  [(size_t)BATCH * LSEQ * (2 * DINNER)];  // in-proj out (x | res)
__device__ float g_xc  [(size_t)BATCH * LSEQ * DINNER];        // conv+silu (tf32) -> y(gated,tf32) in place
__device__ float g_xdbl[(size_t)BATCH * LSEQ * XDBLC];         // tf32-rounded
__device__ float g_dt  [(size_t)BATCH * LSEQ * DINNER];        // full fp32 (scan-only)
__device__ float g_xt  [(size_t)BATCH * LSEQ * DMODEL];        // tf32-rounded x
// fragment-packed tf32 weights (B operands)
__device__ float g_Win [(size_t)DMODEL * (2 * DINNER)];        // [1024,4096]
__device__ float g_Wx  [(size_t)DINNER * 128];                 // [2048,96->128]
__device__ float g_Wdt [(size_t)DTR * DINNER];                 // [64,2048]
__device__ float g_Wout[(size_t)DINNER * DMODEL];              // [2048,1024]

// ---------------- helpers ----------------
__device__ __forceinline__ uint32_t smem_u32(const void* p) {
    uint32_t a;
    asm("{ .reg .u64 t; cvta.to.shared.u64 t, %1; cvt.u32.u64 %0, t; }" : "=r"(a) : "l"(p));
    return a;
}
__device__ __forceinline__ float f2tf(float f) {
    uint32_t r; asm("cvt.rna.tf32.f32 %0, %1;" : "=r"(r) : "f"(f));
    return __uint_as_float(r);
}
__device__ __forceinline__ void cp16(uint32_t dst, const void* src) {
    asm volatile("cp.async.cg.shared.global [%0], [%1], 16;"
                 :: "r"(dst), "l"(src) : "memory");
}
__device__ __forceinline__ void mma8(float* c,
    uint32_t a0, uint32_t a1, uint32_t a2, uint32_t a3, uint32_t b0, uint32_t b1)
{
    asm volatile(
        "mma.sync.aligned.m16n8k8.row.col.f32.tf32.tf32.f32 "
        "{%0,%1,%2,%3}, {%4,%5,%6,%7}, {%8,%9}, {%0,%1,%2,%3};"
        : "+f"(c[0]), "+f"(c[1]), "+f"(c[2]), "+f"(c[3])
        : "r"(a0), "r"(a1), "r"(a2), "r"(a3), "r"(b0), "r"(b1));
}

// ---------------- smem layout: 3 stages, A [128][36], packed B 16KB --------
#define A_ST  18432                 // 128*36*4
#define B_ST  16384                 // packed: 32k x 128n = 4096 floats
#define B_BASE (3 * A_ST)           // 55296
#define SMEM_GEMM (3 * A_ST + 3 * B_ST)   // 104448 -> 2 blocks/SM

// ---------------- B fragment pack ----------------
// P pair index i: lane = i&31 (lane = qr*4+qc), ng16 = (i>>5)&15, kk8 = (i>>9)&3,
// rest = i>>11: bn = rest % nblk, kt32 = rest / nblk.
// k = kt32*32 + kk8*8 + qc ; n = bn*128 + ng16*8 + qr
// P[i] = ( tf32(W[k][n]), tf32(W[k+4][n]) ), zero-padded for n >= N.
__global__ __launch_bounds__(256)
void pack_b(const float* __restrict__ W, float2* __restrict__ P,
            int K, int N, int nblk)
{
    const size_t np = (size_t)K * nblk * 64;   // pairs = K*Npad/2 = K*nblk*64
    size_t i = (size_t)blockIdx.x * blockDim.x + threadIdx.x;
    if (i >= np) return;
    const int lane = (int)(i & 31);
    const int qc = lane & 3, qr = lane >> 2;
    const int ng16 = (int)((i >> 5) & 15);
    const int kk8  = (int)((i >> 9) & 3);
    const size_t rest = i >> 11;
    const int bn = (int)(rest % nblk);
    const int kt32 = (int)(rest / nblk);
    const int k = kt32 * 32 + kk8 * 8 + qc;
    const int n = bn * 128 + ng16 * 8 + qr;
    float2 v = make_float2(0.f, 0.f);
    if (n < N) {
        v.x = f2tf(W[(size_t)k * N + n]);
        v.y = f2tf(W[(size_t)(k + 4) * N + n]);
    }
    P[i] = v;
}

// C[M,N] = A[M,K] @ B[K,N] (+bias). epi: 0=none, 1=softplus, 2=tf32-round out.
// A pre-rounded tf32 [M,K] row-major (lda); Bp fragment-packed (nblk = Npad/128).
// M % 128 == 0, K % 32 == 0.
__global__ __launch_bounds__(256, 2)
void mma_gemm(const float* __restrict__ A, const float2* __restrict__ Bp,
              const float* __restrict__ bias, float* __restrict__ C,
              int M, int N, int K, int lda, int nblk, int ldc, int epi)
{
    extern __shared__ char smc[];
    const uint32_t sb = smem_u32(smc);
    const int tid = threadIdx.x;
    const int bm = blockIdx.y * 128;
    const int bn = blockIdx.x * 128;
    const int wid = tid >> 5, lane = tid & 31;
    const int wm = wid >> 1, wn = wid & 1;     // 4x2 warps, warp tile 32x64
    const int qr = lane >> 2, qc = lane & 3;

    float acc[2][8][4];
    #pragma unroll
    for (int i = 0; i < 2; i++)
        #pragma unroll
        for (int j = 0; j < 8; j++)
            #pragma unroll
            for (int e = 0; e < 4; e++) acc[i][j][e] = 0.f;

    const int rA = tid >> 3, cA = (tid & 7) * 4;     // A loader: +32 rows per t
    const int nch = K >> 5;
    const size_t bchunk = (size_t)blockIdx.x * 2048;  // floats into packed B row

    auto issue = [&](int ch) {
        const int kt = ch << 5;
        const int st = ch - (ch / 3) * 3;
        const uint32_t dA = sb + st * A_ST;
        const uint32_t dB = sb + B_BASE + st * B_ST;
        #pragma unroll
        for (int t = 0; t < 4; t++) {
            const int r = rA + t * 32;
            cp16(dA + (uint32_t)(r * 36 + cA) * 4,
                 A + (size_t)(bm + r) * lda + kt + cA);
        }
        // packed B chunk: contiguous 16KB at ((kt32*nblk + bn/128)*4096 floats)
        const float* src = (const float*)Bp + ((size_t)ch * nblk) * 4096 + bchunk * 2;
        #pragma unroll
        for (int t = 0; t < 4; t++)
            cp16(dB + (uint32_t)(tid + t * 256) * 16, src + (size_t)(tid + t * 256) * 4);
        asm volatile("cp.async.commit_group;" ::: "memory");
    };

    issue(0);
    issue(1);   // nch >= 2 always (K >= 64)

    for (int i = 0; i < nch; i++) {
        if (i + 1 < nch) { asm volatile("cp.async.wait_group 1;" ::: "memory"); }
        else             { asm volatile("cp.async.wait_group 0;" ::: "memory"); }
        __syncthreads();                 // stage i visible; compute(i-1) done everywhere
        if (i + 2 < nch) issue(i + 2);   // reuses stage (i-1)%3 — safe after barrier

        const int st = i - (i / 3) * 3;
        const uint32_t* Ahi = (const uint32_t*)(smc + st * A_ST);
        const float2* Bf = (const float2*)(smc + B_BASE + st * B_ST);

        #pragma unroll
        for (int kk8 = 0; kk8 < 4; kk8++) {
            const int kk = kk8 * 8;
            uint32_t ah[2][4];
            #pragma unroll
            for (int tm = 0; tm < 2; tm++) {
                const int r0 = wm * 32 + tm * 16 + qr;
                ah[tm][0] = Ahi[r0 * 36 + kk + qc];
                ah[tm][1] = Ahi[(r0 + 8) * 36 + kk + qc];
                ah[tm][2] = Ahi[r0 * 36 + kk + qc + 4];
                ah[tm][3] = Ahi[(r0 + 8) * 36 + kk + qc + 4];
            }
            #pragma unroll
            for (int tn = 0; tn < 8; tn++) {
                const float2 b = Bf[(kk8 * 16 + wn * 8 + tn) * 32 + lane];
                const uint32_t b0 = __float_as_uint(b.x);
                const uint32_t b1 = __float_as_uint(b.y);
                #pragma unroll
                for (int tm = 0; tm < 2; tm++)
                    mma8(acc[tm][tn], ah[tm][0], ah[tm][1], ah[tm][2], ah[tm][3], b0, b1);
            }
        }
    }

    // ---- epilogue ----
    #pragma unroll
    for (int tm = 0; tm < 2; tm++) {
        const int r0 = bm + wm * 32 + tm * 16 + qr;
        #pragma unroll
        for (int tn = 0; tn < 8; tn++) {
            const int c0 = bn + wn * 64 + tn * 8 + 2 * qc;
            #pragma unroll
            for (int half = 0; half < 2; half++) {
                const int r = r0 + half * 8;
                float v0 = acc[tm][tn][half * 2 + 0];
                float v1 = acc[tm][tn][half * 2 + 1];
                if (bias && c0 < N) { v0 += bias[c0]; if (c0 + 1 < N) v1 += bias[c0 + 1]; }
                if (epi == 1) {
                    v0 = (v0 > 20.f) ? v0 : log1pf(expf(v0));
                    v1 = (v1 > 20.f) ? v1 : log1pf(expf(v1));
                } else if (epi == 2) {
                    v0 = f2tf(v0); v1 = f2tf(v1);
                }
                if (c0 + 1 < N) {
                    *(float2*)(C + (size_t)r * ldc + c0) = make_float2(v0, v1);
                } else if (c0 < N) {
                    C[(size_t)r * ldc + c0] = v0;
                }
            }
        }
    }
}

// ---------------- round-copy: dst = tf32_rna(src), float4 ----------------
__global__ __launch_bounds__(256)
void round_copy(const float* __restrict__ src, float* __restrict__ dst, size_t n4)
{
    size_t i = (size_t)blockIdx.x * blockDim.x + threadIdx.x;
    if (i >= n4) return;
    const float4 v = ((const float4*)src)[i];
    float4 o;
    o.x = f2tf(v.x); o.y = f2tf(v.y); o.z = f2tf(v.z); o.w = f2tf(v.w);
    ((float4*)dst)[i] = o;
}

// ---------------- causal depthwise conv (K=4) + SiLU -> tf32 --------------
__global__ __launch_bounds__(256)
void conv_silu_kernel(const float* __restrict__ conv_w, const float* __restrict__ conv_b)
{
    const size_t total4 = (size_t)BATCH * LSEQ * (DINNER / 4);
    size_t idx = (size_t)blockIdx.x * blockDim.x + threadIdx.x;
    if (idx >= total4) return;
    const int d4 = (int)(idx % (DINNER / 4));
    const int l  = (int)((idx / (DINNER / 4)) % LSEQ);
    const int b  = (int)(idx / ((size_t)(DINNER / 4) * LSEQ));
    const int d  = d4 * 4;

    float acc0 = conv_b[d], acc1 = conv_b[d + 1], acc2 = conv_b[d + 2], acc3 = conv_b[d + 3];
    #pragma unroll
    for (int k = 0; k < 4; k++) {
        const int ls = l - 3 + k;
        if (ls >= 0) {
            const float4 v = *(const float4*)(&g_xr[((size_t)b * LSEQ + ls) * (2 * DINNER) + d]);
            acc0 = fmaf(conv_w[(d + 0) * 4 + k], v.x, acc0);
            acc1 = fmaf(conv_w[(d + 1) * 4 + k], v.y, acc1);
            acc2 = fmaf(conv_w[(d + 2) * 4 + k], v.z, acc2);
            acc3 = fmaf(conv_w[(d + 3) * 4 + k], v.w, acc3);
        }
    }
    float4 o;
    o.x = f2tf(acc0 / (1.f + __expf(-acc0)));
    o.y = f2tf(acc1 / (1.f + __expf(-acc1)));
    o.z = f2tf(acc2 / (1.f + __expf(-acc2)));
    o.w = f2tf(acc3 / (1.f + __expf(-acc3)));
    *(float4*)(&g_xc[((size_t)b * LSEQ + l) * DINNER + d]) = o;
}

// ---------------- selective scan over L (+x*D, fused gate) --------------
#define SCAN_T 128
__global__ __launch_bounds__(64)
void scan_kernel(const float* __restrict__ A_log, const float* __restrict__ D_par)
{
    __shared__ float sBC[SCAN_T][32];

    const int tid = threadIdx.x;
    const int d = blockIdx.x * 64 + tid;
    const int b = blockIdx.y;

    float A[NST];
    #pragma unroll
    for (int n = 0; n < NST; n++) A[n] = -expf(A_log[d * NST + n]);
    bool fast = true;
    #pragma unroll
    for (int n = 0; n < NST; n++)
        fast = fast && (fabsf(A[n] - (float)(n + 1) * A[0]) <= 1e-4f * (float)(n + 1));

    float h[NST];
    #pragma unroll
    for (int n = 0; n < NST; n++) h[n] = 0.f;
    const float Dp = D_par[d];

    size_t pd = (size_t)b * LSEQ * DINNER + d;
    size_t pr = (size_t)b * LSEQ * (2 * DINNER) + DINNER + d;

    float dt_nx = g_dt[pd];
    float xt_nx = g_xc[pd];
    float rr_nx = g_xr[pr];

    const float* xdb = g_xdbl + (size_t)b * LSEQ * XDBLC + DTR;

    for (int c = 0; c < LSEQ / SCAN_T; c++) {
        __syncthreads();
        const float* src = xdb + (size_t)c * SCAN_T * XDBLC;
        #pragma unroll 4
        for (int i = tid; i < SCAN_T * 8; i += 64) {
            const int row = i >> 3, c4 = (i & 7) * 4;
            *(float4*)&sBC[row][c4] = *(const float4*)(src + (size_t)row * XDBLC + c4);
        }
        __syncthreads();

        for (int t = 0; t < SCAN_T; t++) {
            const float dt = dt_nx, xt = xt_nx, rr = rr_nx;
            const size_t pd_cur = pd;
            const int l = c * SCAN_T + t;
            pd += DINNER; pr += 2 * DINNER;
            if (l + 1 < LSEQ) {
                dt_nx = g_dt[pd];
                xt_nx = g_xc[pd];
                rr_nx = g_xr[pr];
            }
            float dA[NST];
            if (fast) {
                const float e1 = __expf(dt * A[0]);
                const float e2 = e1 * e1, e3 = e2 * e1, e4 = e2 * e2;
                const float e5 = e4 * e1, e6 = e4 * e2, e7 = e4 * e3, e8 = e4 * e4;
                dA[0] = e1;  dA[1] = e2;  dA[2] = e3;  dA[3] = e4;
                dA[4] = e5;  dA[5] = e6;  dA[6] = e7;  dA[7] = e8;
                dA[8]  = e8 * e1;  dA[9]  = e8 * e2;  dA[10] = e8 * e3;  dA[11] = e8 * e4;
                dA[12] = e8 * e5;  dA[13] = e8 * e6;  dA[14] = e8 * e7;  dA[15] = e8 * e8;
            } else {
                #pragma unroll
                for (int n = 0; n < NST; n++) dA[n] = __expf(dt * A[n]);
            }
            const float dtx = dt * xt;
            float y0 = 0.f, y1 = 0.f, y2 = 0.f, y3 = 0.f;
            #pragma unroll
            for (int n = 0; n < NST; n += 4) {
                h[n + 0] = fmaf(h[n + 0], dA[n + 0], dtx * sBC[t][n + 0]);
                h[n + 1] = fmaf(h[n + 1], dA[n + 1], dtx * sBC[t][n + 1]);
                h[n + 2] = fmaf(h[n + 2], dA[n + 2], dtx * sBC[t][n + 2]);
                h[n + 3] = fmaf(h[n + 3], dA[n + 3], dtx * sBC[t][n + 3]);
                y0 = fmaf(h[n + 0], sBC[t][NST + n + 0], y0);
                y1 = fmaf(h[n + 1], sBC[t][NST + n + 1], y1);
                y2 = fmaf(h[n + 2], sBC[t][NST + n + 2], y2);
                y3 = fmaf(h[n + 3], sBC[t][NST + n + 3], y3);
            }
            const float yt = (y0 + y1) + (y2 + y3);
            const float gate = rr / (1.f + __expf(-rr));
            g_xc[pd_cur] = f2tf(fmaf(xt, Dp, yt) * gate);   // tf32 for out-proj A
        }
    }
}

// ---------------- launch -------------------------------------------------
extern "C" void kernel_launch(void* const* d_in, const int* in_sizes, int n_in,
                              void* d_out, int out_size)
{
    const float* x      = (const float*)d_in[0];
    const float* W_in   = (const float*)d_in[1];
    const float* b_in   = (const float*)d_in[2];
    const float* conv_w = (const float*)d_in[3];
    const float* conv_b = (const float*)d_in[4];
    const float* W_x    = (const float*)d_in[5];
    const float* W_dt   = (const float*)d_in[6];
    const float* b_dt   = (const float*)d_in[7];
    const float* A_log  = (const float*)d_in[8];
    const float* D_par  = (const float*)d_in[9];
    const float* W_out  = (const float*)d_in[10];
    const float* b_out  = (const float*)d_in[11];
    float* out = (float*)d_out;

    float *xr, *xc, *xdbl, *dt, *xt, *Win, *Wx, *Wdt, *Wout;
    cudaGetSymbolAddress((void**)&xr,   g_xr);
    cudaGetSymbolAddress((void**)&xc,   g_xc);
    cudaGetSymbolAddress((void**)&xdbl, g_xdbl);
    cudaGetSymbolAddress((void**)&dt,   g_dt);
    cudaGetSymbolAddress((void**)&xt,   g_xt);
    cudaGetSymbolAddress((void**)&Win,  g_Win);
    cudaGetSymbolAddress((void**)&Wx,   g_Wx);
    cudaGetSymbolAddress((void**)&Wdt,  g_Wdt);
    cudaGetSymbolAddress((void**)&Wout, g_Wout);

    cudaFuncSetAttribute(mma_gemm, cudaFuncAttributeMaxDynamicSharedMemorySize, SMEM_GEMM);

    const int M = BATCH * LSEQ;   // 16384

    auto packw = [](const float* s, float* d, int K, int N, int nblk) {
        const size_t np = (size_t)K * nblk * 64;
        pack_b<<<(unsigned)((np + 255) / 256), 256>>>(s, (float2*)d, K, N, nblk);
    };

    // launch 0: round x to tf32
    {
        const size_t n4 = (size_t)M * DMODEL / 4;
        round_copy<<<(unsigned)((n4 + 255) / 256), 256>>>(x, xt, n4);
    }
    // launch 1-2: pack W_in, W_x
    packw(W_in, Win, DMODEL, 2 * DINNER, 32);
    packw(W_x,  Wx,  DINNER, XDBLC, 1);

    // launch 3 (ncu capture target): in-projection [M,1024]@[1024,4096] -> g_xr
    mma_gemm<<<dim3(32, M / 128), 256, SMEM_GEMM>>>(
        xt, (const float2*)Win, b_in, xr, M, 2 * DINNER, DMODEL, DMODEL, 32, 2 * DINNER, 0);

    // conv + silu -> g_xc (tf32)
    {
        const size_t total4 = (size_t)M * (DINNER / 4);
        conv_silu_kernel<<<(unsigned)((total4 + 255) / 256), 256>>>(conv_w, conv_b);
    }

    // x_dbl: [M,2048]@[2048,96] -> g_xdbl (tf32 out)
    mma_gemm<<<dim3(1, M / 128), 256, SMEM_GEMM>>>(
        xc, (const float2*)Wx, nullptr, xdbl, M, XDBLC, DINNER, DINNER, 1, XDBLC, 2);

    packw(W_dt, Wdt, DTR, DINNER, 16);

    // delta: softplus([M,64]@[64,2048]+b_dt) -> g_dt
    mma_gemm<<<dim3(16, M / 128), 256, SMEM_GEMM>>>(
        xdbl, (const float2*)Wdt, b_dt, dt, M, DINNER, DTR, XDBLC, 16, DINNER, 1);

    packw(W_out, Wout, DINNER, DMODEL, 8);

    // selective scan (y in place over g_xc)
    scan_kernel<<<dim3(DINNER / 64, BATCH), 64>>>(A_log, D_par);

    // out-projection: [M,2048]@[2048,1024]+b_out -> d_out
    mma_gemm<<<dim3(8, M / 128), 256, SMEM_GEMM>>>(
        xc, (const float2*)Wout, b_out, out, M, DMODEL, DINNER, DINNER, 8, DMODEL, 0);
}

// round 15
// speedup vs baseline: 2.1518x; 1.9208x over previous
#include <cuda_runtime.h>
#include <math.h>
#include <stdint.h>

#define BATCH  4
#define LSEQ   4096
#define DMODEL 1024
#define DINNER 2048
#define DTR    64
#define NST    16
#define XDBLC  96   // dt_rank + 2*N
#define CL     128                  // scan chunk length
#define NCHNK  (LSEQ / CL)          // 32

// ---------------- scratch (device globals) ----------------
__device__ float g_xr  [(size_t)BATCH * LSEQ * (2 * DINNER)];  // in-proj out (x | res)
__device__ float g_xc  [(size_t)BATCH * LSEQ * DINNER];        // conv+silu (tf32) -> y(gated,tf32) in place
__device__ float g_xdbl[(size_t)BATCH * LSEQ * XDBLC];         // tf32-rounded
__device__ float g_dt  [(size_t)BATCH * LSEQ * DINNER];        // full fp32 (scan-only)
__device__ float g_xt  [(size_t)BATCH * LSEQ * DMODEL];        // tf32-rounded x
// fragment-packed tf32 weights (B operands)
__device__ float g_Win [(size_t)DMODEL * (2 * DINNER)];
__device__ float g_Wx  [(size_t)DINNER * 128];
__device__ float g_Wdt [(size_t)DTR * DINNER];
__device__ float g_Wout[(size_t)DINNER * DMODEL];
// chunked-scan summaries
__device__ float g_hs  [(size_t)BATCH * NCHNK * DINNER * NST]; // h_end -> h_start (in place)
__device__ float g_ss  [(size_t)BATCH * NCHNK * DINNER];       // sum of dt per chunk

// ---------------- helpers ----------------
__device__ __forceinline__ uint32_t smem_u32(const void* p) {
    uint32_t a;
    asm("{ .reg .u64 t; cvta.to.shared.u64 t, %1; cvt.u32.u64 %0, t; }" : "=r"(a) : "l"(p));
    return a;
}
__device__ __forceinline__ float f2tf(float f) {
    uint32_t r; asm("cvt.rna.tf32.f32 %0, %1;" : "=r"(r) : "f"(f));
    return __uint_as_float(r);
}
__device__ __forceinline__ void cp16(uint32_t dst, const void* src) {
    asm volatile("cp.async.cg.shared.global [%0], [%1], 16;"
                 :: "r"(dst), "l"(src) : "memory");
}
__device__ __forceinline__ void mma8(float* c,
    uint32_t a0, uint32_t a1, uint32_t a2, uint32_t a3, uint32_t b0, uint32_t b1)
{
    asm volatile(
        "mma.sync.aligned.m16n8k8.row.col.f32.tf32.tf32.f32 "
        "{%0,%1,%2,%3}, {%4,%5,%6,%7}, {%8,%9}, {%0,%1,%2,%3};"
        : "+f"(c[0]), "+f"(c[1]), "+f"(c[2]), "+f"(c[3])
        : "r"(a0), "r"(a1), "r"(a2), "r"(a3), "r"(b0), "r"(b1));
}
// dA[0..15] from dt given A[]; fast structural path A[n]=(n+1)*A[0]
__device__ __forceinline__ void calc_dA(float dA[NST], float dt, const float A[NST], bool fast)
{
    if (fast) {
        const float e1 = __expf(dt * A[0]);
        const float e2 = e1 * e1, e3 = e2 * e1, e4 = e2 * e2;
        const float e5 = e4 * e1, e6 = e4 * e2, e7 = e4 * e3, e8 = e4 * e4;
        dA[0] = e1;  dA[1] = e2;  dA[2] = e3;  dA[3] = e4;
        dA[4] = e5;  dA[5] = e6;  dA[6] = e7;  dA[7] = e8;
        dA[8]  = e8 * e1;  dA[9]  = e8 * e2;  dA[10] = e8 * e3;  dA[11] = e8 * e4;
        dA[12] = e8 * e5;  dA[13] = e8 * e6;  dA[14] = e8 * e7;  dA[15] = e8 * e8;
    } else {
        #pragma unroll
        for (int n = 0; n < NST; n++) dA[n] = __expf(dt * A[n]);
    }
}
__device__ __forceinline__ bool load_A(float A[NST], const float* A_log, int d)
{
    #pragma unroll
    for (int n = 0; n < NST; n++) A[n] = -expf(A_log[d * NST + n]);
    bool fast = true;
    #pragma unroll
    for (int n = 0; n < NST; n++)
        fast = fast && (fabsf(A[n] - (float)(n + 1) * A[0]) <= 1e-4f * (float)(n + 1));
    return fast;
}

// ---------------- smem layout: 3 stages, A [128][36], packed B 16KB --------
#define A_ST  18432
#define B_ST  16384
#define B_BASE (3 * A_ST)
#define SMEM_GEMM (3 * A_ST + 3 * B_ST)   // 104448 -> 2 blocks/SM

// ---------------- B fragment pack ----------------
__global__ __launch_bounds__(256)
void pack_b(const float* __restrict__ W, float2* __restrict__ P,
            int K, int N, int nblk)
{
    const size_t np = (size_t)K * nblk * 64;
    size_t i = (size_t)blockIdx.x * blockDim.x + threadIdx.x;
    if (i >= np) return;
    const int lane = (int)(i & 31);
    const int qc = lane & 3, qr = lane >> 2;
    const int ng16 = (int)((i >> 5) & 15);
    const int kk8  = (int)((i >> 9) & 3);
    const size_t rest = i >> 11;
    const int bn = (int)(rest % nblk);
    const int kt32 = (int)(rest / nblk);
    const int k = kt32 * 32 + kk8 * 8 + qc;
    const int n = bn * 128 + ng16 * 8 + qr;
    float2 v = make_float2(0.f, 0.f);
    if (n < N) {
        v.x = f2tf(W[(size_t)k * N + n]);
        v.y = f2tf(W[(size_t)(k + 4) * N + n]);
    }
    P[i] = v;
}

// C[M,N] = A[M,K] @ B[K,N] (+bias). epi: 0=none, 1=softplus, 2=tf32-round out.
__global__ __launch_bounds__(256, 2)
void mma_gemm(const float* __restrict__ A, const float2* __restrict__ Bp,
              const float* __restrict__ bias, float* __restrict__ C,
              int M, int N, int K, int lda, int nblk, int ldc, int epi)
{
    extern __shared__ char smc[];
    const uint32_t sb = smem_u32(smc);
    const int tid = threadIdx.x;
    const int bm = blockIdx.y * 128;
    const int bn = blockIdx.x * 128;
    const int wid = tid >> 5, lane = tid & 31;
    const int wm = wid >> 1, wn = wid & 1;
    const int qr = lane >> 2, qc = lane & 3;

    float acc[2][8][4];
    #pragma unroll
    for (int i = 0; i < 2; i++)
        #pragma unroll
        for (int j = 0; j < 8; j++)
            #pragma unroll
            for (int e = 0; e < 4; e++) acc[i][j][e] = 0.f;

    const int rA = tid >> 3, cA = (tid & 7) * 4;
    const int nch = K >> 5;
    const size_t bchunk = (size_t)blockIdx.x * 2048;

    auto issue = [&](int ch) {
        const int kt = ch << 5;
        const int st = ch - (ch / 3) * 3;
        const uint32_t dA = sb + st * A_ST;
        const uint32_t dB = sb + B_BASE + st * B_ST;
        #pragma unroll
        for (int t = 0; t < 4; t++) {
            const int r = rA + t * 32;
            cp16(dA + (uint32_t)(r * 36 + cA) * 4,
                 A + (size_t)(bm + r) * lda + kt + cA);
        }
        const float* src = (const float*)Bp + ((size_t)ch * nblk) * 4096 + bchunk * 2;
        #pragma unroll
        for (int t = 0; t < 4; t++)
            cp16(dB + (uint32_t)(tid + t * 256) * 16, src + (size_t)(tid + t * 256) * 4);
        asm volatile("cp.async.commit_group;" ::: "memory");
    };

    issue(0);
    issue(1);

    for (int i = 0; i < nch; i++) {
        if (i + 1 < nch) { asm volatile("cp.async.wait_group 1;" ::: "memory"); }
        else             { asm volatile("cp.async.wait_group 0;" ::: "memory"); }
        __syncthreads();
        if (i + 2 < nch) issue(i + 2);

        const int st = i - (i / 3) * 3;
        const uint32_t* Ahi = (const uint32_t*)(smc + st * A_ST);
        const float2* Bf = (const float2*)(smc + B_BASE + st * B_ST);

        #pragma unroll
        for (int kk8 = 0; kk8 < 4; kk8++) {
            const int kk = kk8 * 8;
            uint32_t ah[2][4];
            #pragma unroll
            for (int tm = 0; tm < 2; tm++) {
                const int r0 = wm * 32 + tm * 16 + qr;
                ah[tm][0] = Ahi[r0 * 36 + kk + qc];
                ah[tm][1] = Ahi[(r0 + 8) * 36 + kk + qc];
                ah[tm][2] = Ahi[r0 * 36 + kk + qc + 4];
                ah[tm][3] = Ahi[(r0 + 8) * 36 + kk + qc + 4];
            }
            #pragma unroll
            for (int tn = 0; tn < 8; tn++) {
                const float2 b = Bf[(kk8 * 16 + wn * 8 + tn) * 32 + lane];
                const uint32_t b0 = __float_as_uint(b.x);
                const uint32_t b1 = __float_as_uint(b.y);
                #pragma unroll
                for (int tm = 0; tm < 2; tm++)
                    mma8(acc[tm][tn], ah[tm][0], ah[tm][1], ah[tm][2], ah[tm][3], b0, b1);
            }
        }
    }

    #pragma unroll
    for (int tm = 0; tm < 2; tm++) {
        const int r0 = bm + wm * 32 + tm * 16 + qr;
        #pragma unroll
        for (int tn = 0; tn < 8; tn++) {
            const int c0 = bn + wn * 64 + tn * 8 + 2 * qc;
            #pragma unroll
            for (int half = 0; half < 2; half++) {
                const int r = r0 + half * 8;
                float v0 = acc[tm][tn][half * 2 + 0];
                float v1 = acc[tm][tn][half * 2 + 1];
                if (bias && c0 < N) { v0 += bias[c0]; if (c0 + 1 < N) v1 += bias[c0 + 1]; }
                if (epi == 1) {
                    v0 = (v0 > 20.f) ? v0 : log1pf(expf(v0));
                    v1 = (v1 > 20.f) ? v1 : log1pf(expf(v1));
                } else if (epi == 2) {
                    v0 = f2tf(v0); v1 = f2tf(v1);
                }
                if (c0 + 1 < N) {
                    *(float2*)(C + (size_t)r * ldc + c0) = make_float2(v0, v1);
                } else if (c0 < N) {
                    C[(size_t)r * ldc + c0] = v0;
                }
            }
        }
    }
}

// ---------------- round-copy ----------------
__global__ __launch_bounds__(256)
void round_copy(const float* __restrict__ src, float* __restrict__ dst, size_t n4)
{
    size_t i = (size_t)blockIdx.x * blockDim.x + threadIdx.x;
    if (i >= n4) return;
    const float4 v = ((const float4*)src)[i];
    float4 o;
    o.x = f2tf(v.x); o.y = f2tf(v.y); o.z = f2tf(v.z); o.w = f2tf(v.w);
    ((float4*)dst)[i] = o;
}

// ---------------- causal depthwise conv (K=4) + SiLU -> tf32 --------------
__global__ __launch_bounds__(256)
void conv_silu_kernel(const float* __restrict__ conv_w, const float* __restrict__ conv_b)
{
    const size_t total4 = (size_t)BATCH * LSEQ * (DINNER / 4);
    size_t idx = (size_t)blockIdx.x * blockDim.x + threadIdx.x;
    if (idx >= total4) return;
    const int d4 = (int)(idx % (DINNER / 4));
    const int l  = (int)((idx / (DINNER / 4)) % LSEQ);
    const int b  = (int)(idx / ((size_t)(DINNER / 4) * LSEQ));
    const int d  = d4 * 4;

    float acc0 = conv_b[d], acc1 = conv_b[d + 1], acc2 = conv_b[d + 2], acc3 = conv_b[d + 3];
    #pragma unroll
    for (int k = 0; k < 4; k++) {
        const int ls = l - 3 + k;
        if (ls >= 0) {
            const float4 v = *(const float4*)(&g_xr[((size_t)b * LSEQ + ls) * (2 * DINNER) + d]);
            acc0 = fmaf(conv_w[(d + 0) * 4 + k], v.x, acc0);
            acc1 = fmaf(conv_w[(d + 1) * 4 + k], v.y, acc1);
            acc2 = fmaf(conv_w[(d + 2) * 4 + k], v.z, acc2);
            acc3 = fmaf(conv_w[(d + 3) * 4 + k], v.w, acc3);
        }
    }
    float4 o;
    o.x = f2tf(acc0 / (1.f + __expf(-acc0)));
    o.y = f2tf(acc1 / (1.f + __expf(-acc1)));
    o.z = f2tf(acc2 / (1.f + __expf(-acc2)));
    o.w = f2tf(acc3 / (1.f + __expf(-acc3)));
    *(float4*)(&g_xc[((size_t)b * LSEQ + l) * DINNER + d]) = o;
}

// ---------------- chunked scan: pass 1 (local scans, emit summaries) ------
// grid (DINNER/64, NCHNK, BATCH), block 64
__global__ __launch_bounds__(64)
void scan_p1(const float* __restrict__ A_log)
{
    __shared__ float sB[CL][NST];

    const int tid = threadIdx.x;
    const int d = blockIdx.x * 64 + tid;
    const int c = blockIdx.y;
    const int b = blockIdx.z;

    float A[NST];
    const bool fast = load_A(A, A_log, d);

    // stage B for this chunk: CL rows x 16 floats
    {
        const float* src = g_xdbl + ((size_t)b * LSEQ + (size_t)c * CL) * XDBLC + DTR;
        #pragma unroll 4
        for (int i = tid; i < CL * 4; i += 64) {
            const int row = i >> 2, c4 = (i & 3) * 4;
            *(float4*)&sB[row][c4] = *(const float4*)(src + (size_t)row * XDBLC + c4);
        }
    }
    __syncthreads();

    float h[NST];
    #pragma unroll
    for (int n = 0; n < NST; n++) h[n] = 0.f;
    float S = 0.f;

    size_t base = ((size_t)b * LSEQ + (size_t)c * CL) * DINNER + d;
    for (int t = 0; t < CL; t++) {
        const float dt = g_dt[base];
        const float xt = g_xc[base];
        base += DINNER;
        S += dt;
        float dA[NST];
        calc_dA(dA, dt, A, fast);
        const float dtx = dt * xt;
        #pragma unroll
        for (int n = 0; n < NST; n++)
            h[n] = fmaf(h[n], dA[n], dtx * sB[t][n]);
    }

    float* dst = g_hs + (((size_t)b * NCHNK + c) * DINNER + d) * NST;
    #pragma unroll
    for (int n = 0; n < NST; n += 4)
        *(float4*)(dst + n) = make_float4(h[n], h[n + 1], h[n + 2], h[n + 3]);
    g_ss[((size_t)b * NCHNK + c) * DINNER + d] = S;
}

// ---------------- chunked scan: pass 2 (scan chunk summaries) -------------
// grid (DINNER/64, BATCH), block 64. Overwrites g_hs with h_start per chunk.
__global__ __launch_bounds__(64)
void scan_p2(const float* __restrict__ A_log)
{
    const int tid = threadIdx.x;
    const int d = blockIdx.x * 64 + tid;
    const int b = blockIdx.y;

    float A[NST];
    const bool fast = load_A(A, A_log, d);

    float hs[NST];
    #pragma unroll
    for (int n = 0; n < NST; n++) hs[n] = 0.f;

    for (int c = 0; c < NCHNK; c++) {
        float* p = g_hs + (((size_t)b * NCHNK + c) * DINNER + d) * NST;
        float he[NST];
        #pragma unroll
        for (int n = 0; n < NST; n += 4) {
            const float4 v = *(const float4*)(p + n);
            he[n] = v.x; he[n + 1] = v.y; he[n + 2] = v.z; he[n + 3] = v.w;
        }
        const float S = g_ss[((size_t)b * NCHNK + c) * DINNER + d];
        #pragma unroll
        for (int n = 0; n < NST; n += 4)
            *(float4*)(p + n) = make_float4(hs[n], hs[n + 1], hs[n + 2], hs[n + 3]);
        float P[NST];
        calc_dA(P, S, A, fast);   // exp(A[n] * S)
        #pragma unroll
        for (int n = 0; n < NST; n++)
            hs[n] = fmaf(hs[n], P[n], he[n]);
    }
}

// ---------------- chunked scan: pass 3 (rerun with h_start, emit y) -------
// grid (DINNER/64, NCHNK, BATCH), block 64
__global__ __launch_bounds__(64)
void scan_p3(const float* __restrict__ A_log, const float* __restrict__ D_par)
{
    __shared__ float sBC[CL][2 * NST];

    const int tid = threadIdx.x;
    const int d = blockIdx.x * 64 + tid;
    const int c = blockIdx.y;
    const int b = blockIdx.z;

    float A[NST];
    const bool fast = load_A(A, A_log, d);
    const float Dp = D_par[d];

    {
        const float* src = g_xdbl + ((size_t)b * LSEQ + (size_t)c * CL) * XDBLC + DTR;
        #pragma unroll 4
        for (int i = tid; i < CL * 8; i += 64) {
            const int row = i >> 3, c4 = (i & 7) * 4;
            *(float4*)&sBC[row][c4] = *(const float4*)(src + (size_t)row * XDBLC + c4);
        }
    }
    __syncthreads();

    float h[NST];
    {
        const float* p = g_hs + (((size_t)b * NCHNK + c) * DINNER + d) * NST;
        #pragma unroll
        for (int n = 0; n < NST; n += 4) {
            const float4 v = *(const float4*)(p + n);
            h[n] = v.x; h[n + 1] = v.y; h[n + 2] = v.z; h[n + 3] = v.w;
        }
    }

    size_t base = ((size_t)b * LSEQ + (size_t)c * CL) * DINNER + d;
    size_t pr = ((size_t)b * LSEQ + (size_t)c * CL) * (2 * DINNER) + DINNER + d;
    for (int t = 0; t < CL; t++) {
        const float dt = g_dt[base];
        const float xt = g_xc[base];
        const float rr = g_xr[pr];
        pr += 2 * DINNER;
        float dA[NST];
        calc_dA(dA, dt, A, fast);
        const float dtx = dt * xt;
        float y0 = 0.f, y1 = 0.f, y2 = 0.f, y3 = 0.f;
        #pragma unroll
        for (int n = 0; n < NST; n += 4) {
            h[n + 0] = fmaf(h[n + 0], dA[n + 0], dtx * sBC[t][n + 0]);
            h[n + 1] = fmaf(h[n + 1], dA[n + 1], dtx * sBC[t][n + 1]);
            h[n + 2] = fmaf(h[n + 2], dA[n + 2], dtx * sBC[t][n + 2]);
            h[n + 3] = fmaf(h[n + 3], dA[n + 3], dtx * sBC[t][n + 3]);
            y0 = fmaf(h[n + 0], sBC[t][NST + n + 0], y0);
            y1 = fmaf(h[n + 1], sBC[t][NST + n + 1], y1);
            y2 = fmaf(h[n + 2], sBC[t][NST + n + 2], y2);
            y3 = fmaf(h[n + 3], sBC[t][NST + n + 3], y3);
        }
        const float yt = (y0 + y1) + (y2 + y3);
        const float gate = rr / (1.f + __expf(-rr));
        g_xc[base] = f2tf(fmaf(xt, Dp, yt) * gate);
        base += DINNER;
    }
}

// ---------------- launch -------------------------------------------------
extern "C" void kernel_launch(void* const* d_in, const int* in_sizes, int n_in,
                              void* d_out, int out_size)
{
    const float* x      = (const float*)d_in[0];
    const float* W_in   = (const float*)d_in[1];
    const float* b_in   = (const float*)d_in[2];
    const float* conv_w = (const float*)d_in[3];
    const float* conv_b = (const float*)d_in[4];
    const float* W_x    = (const float*)d_in[5];
    const float* W_dt   = (const float*)d_in[6];
    const float* b_dt   = (const float*)d_in[7];
    const float* A_log  = (const float*)d_in[8];
    const float* D_par  = (const float*)d_in[9];
    const float* W_out  = (const float*)d_in[10];
    const float* b_out  = (const float*)d_in[11];
    float* out = (float*)d_out;

    float *xr, *xc, *xdbl, *dt, *xt, *Win, *Wx, *Wdt, *Wout;
    cudaGetSymbolAddress((void**)&xr,   g_xr);
    cudaGetSymbolAddress((void**)&xc,   g_xc);
    cudaGetSymbolAddress((void**)&xdbl, g_xdbl);
    cudaGetSymbolAddress((void**)&dt,   g_dt);
    cudaGetSymbolAddress((void**)&xt,   g_xt);
    cudaGetSymbolAddress((void**)&Win,  g_Win);
    cudaGetSymbolAddress((void**)&Wx,   g_Wx);
    cudaGetSymbolAddress((void**)&Wdt,  g_Wdt);
    cudaGetSymbolAddress((void**)&Wout, g_Wout);

    cudaFuncSetAttribute(mma_gemm, cudaFuncAttributeMaxDynamicSharedMemorySize, SMEM_GEMM);

    const int M = BATCH * LSEQ;   // 16384

    auto packw = [](const float* s, float* d, int K, int N, int nblk) {
        const size_t np = (size_t)K * nblk * 64;
        pack_b<<<(unsigned)((np + 255) / 256), 256>>>(s, (float2*)d, K, N, nblk);
    };

    // launch 0: round x to tf32
    {
        const size_t n4 = (size_t)M * DMODEL / 4;
        round_copy<<<(unsigned)((n4 + 255) / 256), 256>>>(x, xt, n4);
    }
    // launch 1-2: pack W_in, W_x
    packw(W_in, Win, DMODEL, 2 * DINNER, 32);
    packw(W_x,  Wx,  DINNER, XDBLC, 1);

    // launch 3 (ncu capture target): in-projection [M,1024]@[1024,4096] -> g_xr
    mma_gemm<<<dim3(32, M / 128), 256, SMEM_GEMM>>>(
        xt, (const float2*)Win, b_in, xr, M, 2 * DINNER, DMODEL, DMODEL, 32, 2 * DINNER, 0);

    // conv + silu -> g_xc (tf32)
    {
        const size_t total4 = (size_t)M * (DINNER / 4);
        conv_silu_kernel<<<(unsigned)((total4 + 255) / 256), 256>>>(conv_w, conv_b);
    }

    // x_dbl: [M,2048]@[2048,96] -> g_xdbl (tf32 out)
    mma_gemm<<<dim3(1, M / 128), 256, SMEM_GEMM>>>(
        xc, (const float2*)Wx, nullptr, xdbl, M, XDBLC, DINNER, DINNER, 1, XDBLC, 2);

    packw(W_dt, Wdt, DTR, DINNER, 16);

    // delta: softplus([M,64]@[64,2048]+b_dt) -> g_dt
    mma_gemm<<<dim3(16, M / 128), 256, SMEM_GEMM>>>(
        xdbl, (const float2*)Wdt, b_dt, dt, M, DINNER, DTR, XDBLC, 16, DINNER, 1);

    packw(W_out, Wout, DINNER, DMODEL, 8);

    // chunked selective scan (y in place over g_xc)
    scan_p1<<<dim3(DINNER / 64, NCHNK, BATCH), 64>>>(A_log);
    scan_p2<<<dim3(DINNER / 64, BATCH), 64>>>(A_log);
    scan_p3<<<dim3(DINNER / 64, NCHNK, BATCH), 64>>>(A_log, D_par);

    // out-projection: [M,2048]@[2048,1024]+b_out -> d_out
    mma_gemm<<<dim3(8, M / 128), 256, SMEM_GEMM>>>(
        xc, (const float2*)Wout, b_out, out, M, DMODEL, DINNER, DINNER, 8, DMODEL, 0);
}